// round 16
// baseline (speedup 1.0000x reference)
#include <cuda_runtime.h>
#include <cuda_fp16.h>
#include <math.h>
#include <stdint.h>

typedef unsigned long long u64;
typedef unsigned int u32;

#define NB      8
#define T0      8192
#define HID     128
#define TARGET  6146
#define NLAY    20

// ---------------- scratch (device globals; no allocation) ----------------
__device__ float  g_resI[(size_t)NB * T0 * HID];   // input projection (preserved)
__device__ float  g_res0[(size_t)NB * T0 * HID];
__device__ float  g_res1[(size_t)NB * T0 * HID];
// fragment-ordered fp16 weights
__device__ u32 g_wfrag1[(size_t)NLAY * 32768]; // [l][mat][tile16][kc][ks][lane][4]
__device__ u32 g_wfrag2[(size_t)NLAY * 8192];  // [l][c][ks][mt][lane][4]
__device__ u32 g_whi[16384];                   // Wi frags [tile8][kc8][ks2][lane][4]
__device__ u32 g_wh1[32768];
__device__ u32 g_wh2[65536];

// ---------------- PDL helpers (sm_90 baseline PTX; fine at compute_103) ----
#define PDL_TRIGGER() asm volatile("griddepcontrol.launch_dependents;" ::: "memory")
#define PDL_WAIT()    asm volatile("griddepcontrol.wait;" ::: "memory")
__device__ __forceinline__ void l2pf(const void* p) {
    asm volatile("prefetch.global.L2 [%0];" :: "l"(p));
}

// ---------------- fp16 mma helpers ----------------
__device__ __forceinline__ u32 pkhalf2(float lo, float hi) {
    u32 u;
    asm("{ .reg .b16 l, h; cvt.rn.f16.f32 l, %1; cvt.rn.f16.f32 h, %2; mov.b32 %0, {l, h}; }"
        : "=r"(u) : "f"(lo), "f"(hi));
    return u;
}
__device__ __forceinline__ void mma16816(float* c, const u32* a, u32 b0, u32 b1) {
    asm volatile(
        "mma.sync.aligned.m16n8k16.row.col.f32.f16.f16.f32 "
        "{%0,%1,%2,%3}, {%4,%5,%6,%7}, {%8,%9}, {%0,%1,%2,%3};"
        : "+f"(c[0]), "+f"(c[1]), "+f"(c[2]), "+f"(c[3])
        : "r"(a[0]), "r"(a[1]), "r"(a[2]), "r"(a[3]), "r"(b0), "r"(b1));
}
__device__ __forceinline__ void ldm_x4(u32* r, u32 addr) {
    asm volatile("ldmatrix.sync.aligned.m8n8.x4.shared.b16 {%0,%1,%2,%3}, [%4];"
        : "=r"(r[0]), "=r"(r[1]), "=r"(r[2]), "=r"(r[3]) : "r"(addr));
}
__device__ __forceinline__ u32 h2tanh(u32 x) {
    u32 y; asm("tanh.approx.f16x2 %0, %1;" : "=r"(y) : "r"(x)); return y;
}
__device__ __forceinline__ u32 h2fma(u32 a, u32 b, u32 c) {
    u32 d; asm("fma.rn.f16x2 %0, %1, %2, %3;" : "=r"(d) : "r"(a), "r"(b), "r"(c)); return d;
}
__device__ __forceinline__ u32 h2mul(u32 a, u32 b) {
    u32 d; asm("mul.rn.f16x2 %0, %1, %2;" : "=r"(d) : "r"(a), "r"(b)); return d;
}
__device__ __forceinline__ uint32_t smem_u32(const void* p) {
    uint32_t a;
    asm("{ .reg .u64 t; cvta.to.shared.u64 t, %1; cvt.u32.u64 %0, t; }" : "=r"(a) : "l"(p));
    return a;
}

// =====================================================================
// Weight prep: fp32 -> fp16 fragment order, once per launch
// =====================================================================
__global__ __launch_bounds__(256) void prep_w(
    const float* __restrict__ Wf, const float* __restrict__ Wg,
    const float* __restrict__ Wr, const float* __restrict__ W1,
    const float* __restrict__ W2, const float* __restrict__ Wi)
{
    const int stride = gridDim.x * blockDim.x;
    const int tid0 = blockIdx.x * blockDim.x + threadIdx.x;
    // GEMM1 frags: [l][mat][tile16][kc][ks][lane][reg], k-index = 2*i+tap
    for (int idx = tid0; idx < NLAY * 32768; idx += stride) {
        int l = idx >> 15, r = idx & 32767;
        int mat  = (r >> 14) & 1;
        int tile = (r >> 11) & 7;
        int kc   = (r >> 8) & 7;
        int ks   = (r >> 7) & 1;
        int lane = (r >> 2) & 31;
        int reg  = r & 3;
        int row = tile * 16 + (lane >> 2) + ((reg & 1) ? 8 : 0);
        int kb  = kc * 32 + ks * 16 + 2 * (lane & 3) + ((reg & 2) ? 8 : 0);
        const float* W = (mat ? Wg : Wf) + (size_t)l * 32768;
        float2 v = *(const float2*)(W + ((size_t)row * 128 + (kb >> 1)) * 2);
        g_wfrag1[idx] = pkhalf2(v.x, v.y);
    }
    // GEMM2 frags
    for (int idx = tid0; idx < NLAY * 8192; idx += stride) {
        int l = idx >> 13, r = idx & 8191;
        int c  = (r >> 11) & 3;
        int ks = (r >> 8) & 7;
        int mt = (r >> 7) & 1;
        int lane = (r >> 2) & 31;
        int reg  = r & 3;
        int row = c * 32 + mt * 16 + (lane >> 2) + ((reg & 1) ? 8 : 0);
        int k   = ks * 16 + 2 * (lane & 3) + ((reg & 2) ? 8 : 0);
        const float* W = Wr + (size_t)l * 16384;
        g_wfrag2[idx] = pkhalf2(W[row * 128 + k], W[row * 128 + k + 1]);
    }
    // Wi frags: [tile8][kc8][ks2][lane][reg], K=256
    for (int idx = tid0; idx < 16384; idx += stride) {
        int tile = (idx >> 11) & 7;
        int kc   = (idx >> 8) & 7;
        int ks   = (idx >> 7) & 1;
        int lane = (idx >> 2) & 31;
        int reg  = idx & 3;
        int row = tile * 16 + (lane >> 2) + ((reg & 1) ? 8 : 0);
        int k   = kc * 32 + ks * 16 + 2 * (lane & 3) + ((reg & 2) ? 8 : 0);
        g_whi[idx] = pkhalf2(Wi[row * 256 + k], Wi[row * 256 + k + 1]);
    }
    // head1 frags: W1 [512][128]
    for (int idx = tid0; idx < 32768; idx += stride) {
        int tile = idx >> 10;
        int ks   = (idx >> 7) & 7;
        int lane = (idx >> 2) & 31;
        int reg  = idx & 3;
        int row = tile * 16 + (lane >> 2) + ((reg & 1) ? 8 : 0);
        int k   = ks * 16 + 2 * (lane & 3) + ((reg & 2) ? 8 : 0);
        g_wh1[idx] = pkhalf2(W1[row * 128 + k], W1[row * 128 + k + 1]);
    }
    // head2 frags: W2 [256][512]
    for (int idx = tid0; idx < 65536; idx += stride) {
        int tile = idx >> 12;
        int ks   = (idx >> 7) & 31;
        int lane = (idx >> 2) & 31;
        int reg  = idx & 3;
        int row = tile * 16 + (lane >> 2) + ((reg & 1) ? 8 : 0);
        int k   = ks * 16 + 2 * (lane & 3) + ((reg & 2) ? 8 : 0);
        g_wh2[idx] = pkhalf2(W2[row * 512 + k], W2[row * 512 + k + 1]);
    }
}

// smem byte map for layer_mma
#define SM_ACT  0
#define SM_OUT  33792
#define LMM_SMEM (SM_OUT + 17408)   // 51200

// =====================================================================
// Layer kernel (R12/R15 structure) + PDL overlap
// ssel: 2 = g_resI, 0 = g_res0, 1 = g_res1; dsel: 0/1
// =====================================================================
__global__ __launch_bounds__(256, 2) void layer_mma(
    int ssel, int dsel, int layer,
    const float* __restrict__ bf, const float* __restrict__ bg,
    const float* __restrict__ br,
    int d, int Tnew)
{
    extern __shared__ char sm[];
    const u32 sb = smem_u32(sm);

    const int tid = threadIdx.x, wid = tid >> 5, lane = tid & 31;
    const int g8 = lane >> 2, tig = lane & 3;
    const int b = blockIdx.y, t0 = blockIdx.x * 64;
    const int Tcur = Tnew + d;

    // ---- pre-dependency: L2-prefetch this layer's weight slab ----
    {
        const char* wl  = (const char*)(g_wfrag1 + (size_t)layer * 32768);
        const char* w2l = (const char*)(g_wfrag2 + (size_t)layer * 8192);
#pragma unroll
        for (int i = 0; i < 4; i++) l2pf(wl + tid * 128 + i * 32768);
        l2pf(w2l + tid * 128);
    }
    PDL_WAIT();

    const float* srcb = (ssel == 2 ? g_resI : (ssel ? g_res1 : g_res0)) + (size_t)b * T0 * HID;
    float*       dstb = (dsel ? g_res1 : g_res0) + (size_t)b * T0 * HID;

    // ---- stage activations, taps interleaved: s_act[t][k=2c+tap] ----
    for (int e = tid; e < 64 * 32; e += 256) {
        int j = e >> 5, c4 = e & 31;
        int ta = t0 + j;     if (ta > Tcur - 1) ta = Tcur - 1;
        int tb = t0 + j + d; if (tb > Tcur - 1) tb = Tcur - 1;
        float4 A = *(const float4*)(srcb + (size_t)ta * HID + c4 * 4);
        float4 B = *(const float4*)(srcb + (size_t)tb * HID + c4 * 4);
        uint4 st;
        st.x = pkhalf2(A.x, B.x);
        st.y = pkhalf2(A.y, B.y);
        st.z = pkhalf2(A.z, B.z);
        st.w = pkhalf2(A.w, B.w);
        *(uint4*)(sm + SM_ACT + j * 528 + c4 * 16) = st;
    }
    __syncthreads();   // #1

    const int browoff = ((lane & 16) ? 8 : 0) + (lane & 7);
    const u32 bk16 = (lane & 8) ? 16u : 0u;
    const u32 b_base = sb + SM_ACT + browoff * 528 + bk16;

    // ---- GEMM1: warp w computes f AND g for ch [16w,16w+16) x 64 t ----
    const uint4* wpf = (const uint4*)g_wfrag1 + (size_t)layer * 8192 + wid * 512 + lane;
    const uint4* wpg = wpf + 4096;

    float acc_f[8][4], acc_g[8][4];
#pragma unroll
    for (int i = 0; i < 8; i++)
#pragma unroll
        for (int k = 0; k < 4; k++) { acc_f[i][k] = 0.f; acc_g[i][k] = 0.f; }

    uint4 Af[2], Ag[2];
    Af[0] = wpf[0]; Af[1] = wpf[32]; Ag[0] = wpg[0]; Ag[1] = wpg[32];
    for (int kc = 0; kc < 8; kc++) {
        uint4 Afn[2], Agn[2];
        if (kc < 7) {
            Afn[0] = wpf[(kc + 1) * 64];      Afn[1] = wpf[(kc + 1) * 64 + 32];
            Agn[0] = wpg[(kc + 1) * 64];      Agn[1] = wpg[(kc + 1) * 64 + 32];
        }
        const u32 bbase_k = b_base + kc * 64;
#pragma unroll
        for (int ks = 0; ks < 2; ks++) {
            const u32* af = (const u32*)&Af[ks];
            const u32* ag = (const u32*)&Ag[ks];
#pragma unroll
            for (int ntp = 0; ntp < 4; ntp++) {
                u32 bt[4];
                ldm_x4(bt, bbase_k + ntp * 8448 + ks * 32);
                mma16816(acc_f[2 * ntp],     af, bt[0], bt[1]);
                mma16816(acc_f[2 * ntp + 1], af, bt[2], bt[3]);
                mma16816(acc_g[2 * ntp],     ag, bt[0], bt[1]);
                mma16816(acc_g[2 * ntp + 1], ag, bt[2], bt[3]);
            }
        }
        if (kc < 7) { Af[0] = Afn[0]; Af[1] = Afn[1]; Ag[0] = Agn[0]; Ag[1] = Agn[1]; }
    }

    // bulk work done: let the next layer start its weight prefetch
    PDL_TRIGGER();

    // ---- early GEMM2 A-fragment prefetch (hides L2 latency behind epilogue) ----
    const uint4* wp2 = (const uint4*)g_wfrag2 +
        (size_t)layer * 2048 + (wid & 3) * 512 + lane;
    uint4 A2[2];
    A2[0] = wp2[0]; A2[1] = wp2[32];

    // ---- epilogue1 (f16x2): out = tanh(f+bf) * (.5 + .5*tanh(.5*(g+bg))) ----
    {
        unsigned short* sout = (unsigned short*)(sm + SM_OUT);
        const int ch0 = wid * 16 + g8;
        float bf0 = bf[ch0], bf8 = bf[ch0 + 8];
        float bg0h = 0.5f * bg[ch0], bg8h = 0.5f * bg[ch0 + 8];
        const u32 H05 = 0x38003800u;
#pragma unroll
        for (int nt = 0; nt < 8; nt++) {
            int t_ = nt * 8 + 2 * tig;
            u32 tf01 = h2tanh(pkhalf2(acc_f[nt][0] + bf0, acc_f[nt][1] + bf0));
            u32 tf23 = h2tanh(pkhalf2(acc_f[nt][2] + bf8, acc_f[nt][3] + bf8));
            u32 tg01 = h2tanh(pkhalf2(fmaf(acc_g[nt][0], 0.5f, bg0h),
                                      fmaf(acc_g[nt][1], 0.5f, bg0h)));
            u32 tg23 = h2tanh(pkhalf2(fmaf(acc_g[nt][2], 0.5f, bg8h),
                                      fmaf(acc_g[nt][3], 0.5f, bg8h)));
            u32 p01 = h2mul(tf01, h2fma(tg01, H05, H05));
            u32 p23 = h2mul(tf23, h2fma(tg23, H05, H05));
            unsigned short lo, hi;
            asm("mov.b32 {%0, %1}, %2;" : "=h"(lo), "=h"(hi) : "r"(p01));
            sout[(t_    ) * 136 + ch0] = lo;
            sout[(t_ + 1) * 136 + ch0] = hi;
            asm("mov.b32 {%0, %1}, %2;" : "=h"(lo), "=h"(hi) : "r"(p23));
            sout[(t_    ) * 136 + ch0 + 8] = lo;
            sout[(t_ + 1) * 136 + ch0 + 8] = hi;
        }
    }
    __syncthreads();   // #2

    // ---- GEMM2: x = Wr . out ----
    const int chb2 = (wid & 3) * 32;
    const int nb2 = (wid >> 2) * 32;
    const u32 b2base = sb + SM_OUT + (nb2 + browoff) * 272 + bk16;

    float acc2[8][4];
#pragma unroll
    for (int i = 0; i < 8; i++)
#pragma unroll
        for (int k = 0; k < 4; k++) acc2[i][k] = 0.f;

    for (int ks = 0; ks < 8; ks++) {
        uint4 A2n[2];
        if (ks < 7) { A2n[0] = wp2[(ks + 1) * 64]; A2n[1] = wp2[(ks + 1) * 64 + 32]; }
#pragma unroll
        for (int ntp = 0; ntp < 2; ntp++) {
            u32 bt[4];
            ldm_x4(bt, b2base + ntp * 4352 + ks * 32);
            mma16816(acc2[ntp * 2],         (const u32*)&A2[0], bt[0], bt[1]);
            mma16816(acc2[ntp * 2 + 1],     (const u32*)&A2[0], bt[2], bt[3]);
            mma16816(acc2[4 + ntp * 2],     (const u32*)&A2[1], bt[0], bt[1]);
            mma16816(acc2[4 + ntp * 2 + 1], (const u32*)&A2[1], bt[2], bt[3]);
        }
        if (ks < 7) { A2[0] = A2n[0]; A2[1] = A2n[1]; }
    }

    // ---- epilogue2: x + br -> s_x ----
    float* sx = (float*)(sm + SM_ACT);
    {
        float br0 = br[chb2 + g8],       br8  = br[chb2 + g8 + 8];
        float br16 = br[chb2 + 16 + g8], br24 = br[chb2 + 24 + g8];
#pragma unroll
        for (int mt = 0; mt < 2; mt++) {
            int ch0 = chb2 + mt * 16 + g8;
            float bv0 = mt ? br16 : br0;
            float bv8 = mt ? br24 : br8;
#pragma unroll
            for (int nt = 0; nt < 4; nt++) {
                int t_ = nb2 + nt * 8 + 2 * tig;
                float* a4 = acc2[mt * 4 + nt];
                sx[(t_    ) * 132 + ch0    ] = a4[0] + bv0;
                sx[(t_ + 1) * 132 + ch0    ] = a4[1] + bv0;
                sx[(t_    ) * 132 + ch0 + 8] = a4[2] + bv8;
                sx[(t_ + 1) * 132 + ch0 + 8] = a4[3] + bv8;
            }
        }
    }

    // ---- hoisted residual loads (overlap with barrier #3) ----
    float4 rv[8];
#pragma unroll
    for (int it = 0; it < 8; it++) {
        int e = tid + it * 256;
        int j = e >> 5, c4 = e & 31;
        int t = t0 + j;
        int tt = (t < Tnew) ? (t + d) : (Tcur - 1);
        rv[it] = *(const float4*)(srcb + (size_t)tt * HID + c4 * 4);
    }
    __syncthreads();   // #3

    // ---- residual only (skip telescoped away) ----
#pragma unroll
    for (int it = 0; it < 8; it++) {
        int e = tid + it * 256;
        int j = e >> 5, c4 = e & 31;
        int t = t0 + j;
        if (t < Tnew) {
            float4 x = *(float4*)(sx + j * 132 + c4 * 4);
            float4 o;
            o.x = x.x + rv[it].x; o.y = x.y + rv[it].y;
            o.z = x.z + rv[it].z; o.w = x.w + rv[it].w;
            *(float4*)(dstb + (size_t)t * HID + c4 * 4) = o;
        }
    }
}

// =====================================================================
// Input GEMM (mma): resI = Wi . inputs + bi, 128ch x 64t per CTA, K=256
// =====================================================================
#define INM_SMEM (64 * 528)
__global__ __launch_bounds__(256, 2) void in_mma(
    const float* __restrict__ inp, const float* __restrict__ bi)
{
    extern __shared__ char sm[];
    const u32 sb = smem_u32(sm);
    const int tid = threadIdx.x, wid = tid >> 5, lane = tid & 31;
    const int g8 = lane >> 2, tig = lane & 3;
    const int b = blockIdx.y, t0 = blockIdx.x * 64;

    const float* ib = inp + (size_t)b * 256 * T0;
    // stage: smem half[64t][264], k = ch (coalesced along t)
    for (int e = tid; e < 1024; e += 256) {
        int cblk = e >> 4, tq = e & 15;
        const float* p0 = ib + (size_t)(cblk * 4) * T0 + t0 + tq * 4;
        float4 r0 = *(const float4*)(p0);
        float4 r1 = *(const float4*)(p0 + T0);
        float4 r2 = *(const float4*)(p0 + 2 * T0);
        float4 r3 = *(const float4*)(p0 + 3 * T0);
        const float* f0 = (const float*)&r0;
        const float* f1 = (const float*)&r1;
        const float* f2 = (const float*)&r2;
        const float* f3 = (const float*)&r3;
#pragma unroll
        for (int tt = 0; tt < 4; tt++) {
            uint2 st;
            st.x = pkhalf2(f0[tt], f1[tt]);
            st.y = pkhalf2(f2[tt], f3[tt]);
            *(uint2*)(sm + (tq * 4 + tt) * 528 + cblk * 8) = st;
        }
    }
    __syncthreads();

    const int browoff = ((lane & 16) ? 8 : 0) + (lane & 7);
    const u32 bk16 = (lane & 8) ? 16u : 0u;
    const u32 b_base = sb + browoff * 528 + bk16;
    const uint4* wpA = (const uint4*)g_whi + wid * 512 + lane;

    float acc[8][4];
#pragma unroll
    for (int i = 0; i < 8; i++)
#pragma unroll
        for (int k = 0; k < 4; k++) acc[i][k] = 0.f;

    uint4 A[2] = { wpA[0], wpA[32] };
    for (int kc = 0; kc < 8; kc++) {
        uint4 An[2];
        if (kc < 7) { An[0] = wpA[(kc + 1) * 64]; An[1] = wpA[(kc + 1) * 64 + 32]; }
        const u32 bbase_k = b_base + kc * 64;
#pragma unroll
        for (int ks = 0; ks < 2; ks++) {
            const u32* af = (const u32*)&A[ks];
#pragma unroll
            for (int ntp = 0; ntp < 4; ntp++) {
                u32 bt[4];
                ldm_x4(bt, bbase_k + ntp * 8448 + ks * 32);
                mma16816(acc[2 * ntp],     af, bt[0], bt[1]);
                mma16816(acc[2 * ntp + 1], af, bt[2], bt[3]);
            }
        }
        if (kc < 7) { A[0] = An[0]; A[1] = An[1]; }
    }

    // mainloop done: let layer 0 start its weight prefetch
    PDL_TRIGGER();

    float* rb = g_resI + (size_t)b * T0 * HID;
    const int ch0 = wid * 16 + g8;
    const float bv0 = bi[ch0], bv8 = bi[ch0 + 8];
#pragma unroll
    for (int nt = 0; nt < 8; nt++) {
        int t_ = t0 + nt * 8 + 2 * tig;
        rb[(size_t)t_ * HID + ch0]           = acc[nt][0] + bv0;
        rb[(size_t)(t_ + 1) * HID + ch0]     = acc[nt][1] + bv0;
        rb[(size_t)t_ * HID + ch0 + 8]       = acc[nt][2] + bv8;
        rb[(size_t)(t_ + 1) * HID + ch0 + 8] = acc[nt][3] + bv8;
    }
}

// =====================================================================
// Fused head: out = W2.relu(W1.relu(resF - resI_shift)+b1)+b2  (+PDL wait)
// =====================================================================
#define HF_SIN  0
#define HF_SMID 8704
#define HF_SMEM (HF_SMID + 32 * 1040)   // 41984
__global__ __launch_bounds__(256, 2) void head_fused(
    const float* __restrict__ b1, const float* __restrict__ b2,
    float* __restrict__ out)
{
    extern __shared__ char sm[];
    const u32 sb = smem_u32(sm);
    const int tid = threadIdx.x, wid = tid >> 5, lane = tid & 31;
    const int g8 = lane >> 2, tig = lane & 3;
    const int b = blockIdx.y, t0 = blockIdx.x * 32;

    // pre-dependency: prefetch head weights
    l2pf((const char*)g_wh1 + tid * 128 + (tid & 1) * 0);
    l2pf((const char*)g_wh1 + 32768 + tid * 128);
    l2pf((const char*)g_wh2 + tid * 128);
    l2pf((const char*)g_wh2 + 32768 + tid * 128);
    l2pf((const char*)g_wh2 + 65536 + tid * 128);
    l2pf((const char*)g_wh2 + 98304 + tid * 128);
    l2pf((const char*)g_wh2 + 131072 + tid * 128);
    l2pf((const char*)g_wh2 + 163840 + tid * 128);
    PDL_WAIT();

    // ---- phase A input: relu(resF - resI_shift) -> fp16 smem ----
    const float* rf = g_res1 + (size_t)b * T0 * HID;
    const float* ri = g_resI + (size_t)b * T0 * HID + (size_t)(T0 - TARGET) * HID;
    for (int e = tid; e < 32 * 32; e += 256) {
        int j = e >> 5, c4 = e & 31;
        int t = t0 + j;
        float4 v = make_float4(0.f, 0.f, 0.f, 0.f);
        if (t < TARGET) {
            float4 a = *(const float4*)(rf + (size_t)t * HID + c4 * 4);
            float4 c = *(const float4*)(ri + (size_t)t * HID + c4 * 4);
            v.x = a.x - c.x; v.y = a.y - c.y; v.z = a.z - c.z; v.w = a.w - c.w;
        }
        uint2 st;
        st.x = pkhalf2(fmaxf(v.x, 0.f), fmaxf(v.y, 0.f));
        st.y = pkhalf2(fmaxf(v.z, 0.f), fmaxf(v.w, 0.f));
        *(uint2*)(sm + HF_SIN + j * 272 + c4 * 8) = st;
    }
    __syncthreads();

    const int browoff = ((lane & 16) ? 8 : 0) + (lane & 7);
    const u32 bk16 = (lane & 8) ? 16u : 0u;

    // ---- head1 GEMM: warp w -> 64 mid-ch x 32 t, K=128 ----
    {
        const u32 b_base = sb + HF_SIN + browoff * 272 + bk16;
        const uint4* wp = (const uint4*)g_wh1 + wid * 4 * 256 + lane;

        float acc[16][4];
#pragma unroll
        for (int i = 0; i < 16; i++)
#pragma unroll
            for (int k = 0; k < 4; k++) acc[i][k] = 0.f;

        uint4 A[4];
#pragma unroll
        for (int mt = 0; mt < 4; mt++) A[mt] = wp[mt * 256];
        for (int ks = 0; ks < 8; ks++) {
            uint4 An[4];
            if (ks < 7) {
#pragma unroll
                for (int mt = 0; mt < 4; mt++) An[mt] = wp[mt * 256 + (ks + 1) * 32];
            }
#pragma unroll
            for (int ntp = 0; ntp < 2; ntp++) {
                u32 bt[4];
                ldm_x4(bt, b_base + ntp * 4352 + ks * 32);
#pragma unroll
                for (int mt = 0; mt < 4; mt++) {
                    mma16816(acc[mt * 4 + 2 * ntp],     (const u32*)&A[mt], bt[0], bt[1]);
                    mma16816(acc[mt * 4 + 2 * ntp + 1], (const u32*)&A[mt], bt[2], bt[3]);
                }
            }
            if (ks < 7) {
#pragma unroll
                for (int mt = 0; mt < 4; mt++) A[mt] = An[mt];
            }
        }

        // mid = relu(acc + b1) -> fp16 smem (same rounding as before)
        __half* smd = (__half*)(sm + HF_SMID);
#pragma unroll
        for (int mt = 0; mt < 4; mt++) {
            int ch0 = wid * 64 + mt * 16 + g8;
            float bv0 = b1[ch0], bv8 = b1[ch0 + 8];
#pragma unroll
            for (int nt = 0; nt < 4; nt++) {
                int t_ = nt * 8 + 2 * tig;
                float* a4 = acc[mt * 4 + nt];
                smd[(t_    ) * 520 + ch0    ] = __float2half_rn(fmaxf(a4[0] + bv0, 0.f));
                smd[(t_ + 1) * 520 + ch0    ] = __float2half_rn(fmaxf(a4[1] + bv0, 0.f));
                smd[(t_    ) * 520 + ch0 + 8] = __float2half_rn(fmaxf(a4[2] + bv8, 0.f));
                smd[(t_ + 1) * 520 + ch0 + 8] = __float2half_rn(fmaxf(a4[3] + bv8, 0.f));
            }
        }
    }
    __syncthreads();

    // ---- head2 GEMM: warp w -> out-ch tiles {2w, 2w+1} x 32 t, K=512 ----
    {
        const u32 b2b = sb + HF_SMID + browoff * 1040 + bk16;
        const uint4* wp0 = (const uint4*)g_wh2 + (wid * 2) * 1024 + lane;
        const uint4* wp1 = wp0 + 1024;

        float acc2[8][4];
#pragma unroll
        for (int i = 0; i < 8; i++)
#pragma unroll
            for (int k = 0; k < 4; k++) acc2[i][k] = 0.f;

        uint4 A[2] = { wp0[0], wp1[0] };
        for (int ks = 0; ks < 32; ks++) {
            uint4 An[2];
            if (ks < 31) { An[0] = wp0[(ks + 1) * 32]; An[1] = wp1[(ks + 1) * 32]; }
#pragma unroll
            for (int ntp = 0; ntp < 2; ntp++) {
                u32 bt[4];
                ldm_x4(bt, b2b + ntp * 16640 + ks * 32);
                mma16816(acc2[ntp * 2],         (const u32*)&A[0], bt[0], bt[1]);
                mma16816(acc2[ntp * 2 + 1],     (const u32*)&A[0], bt[2], bt[3]);
                mma16816(acc2[4 + ntp * 2],     (const u32*)&A[1], bt[0], bt[1]);
                mma16816(acc2[4 + ntp * 2 + 1], (const u32*)&A[1], bt[2], bt[3]);
            }
            if (ks < 31) { A[0] = An[0]; A[1] = An[1]; }
        }

#pragma unroll
        for (int j = 0; j < 2; j++) {
            int ch0 = (wid * 2 + j) * 16 + g8;
            float bv0 = b2[ch0], bv8 = b2[ch0 + 8];
#pragma unroll
            for (int nt = 0; nt < 4; nt++) {
                int t_ = t0 + nt * 8 + 2 * tig;
                float* a4 = acc2[j * 4 + nt];
                if (t_ < TARGET) {
                    float* op = out + ((size_t)b * TARGET + t_) * 256;
                    op[ch0]     = a4[0] + bv0;
                    op[ch0 + 8] = a4[2] + bv8;
                }
                if (t_ + 1 < TARGET) {
                    float* op = out + ((size_t)b * TARGET + t_ + 1) * 256;
                    op[ch0]     = a4[1] + bv0;
                    op[ch0 + 8] = a4[3] + bv8;
                }
            }
        }
    }
}

// =====================================================================
// Host launcher
// =====================================================================
static void launch_pdl(void* fn, dim3 grid, dim3 block, size_t smem,
                       void** args)
{
    cudaLaunchConfig_t cfg = {};
    cfg.gridDim = grid;
    cfg.blockDim = block;
    cfg.dynamicSmemBytes = smem;
    cfg.stream = 0;
    cudaLaunchAttribute attr[1];
    attr[0].id = cudaLaunchAttributeProgrammaticStreamSerialization;
    attr[0].val.programmaticStreamSerializationAllowed = 1;
    cfg.attrs = attr;
    cfg.numAttrs = 1;
    cudaLaunchKernelExC(&cfg, fn, args);
}

extern "C" void kernel_launch(void* const* d_in, const int* in_sizes, int n_in,
                              void* d_out, int out_size)
{
    (void)in_sizes; (void)n_in; (void)out_size;
    const float* inp = (const float*)d_in[0];
    const float* Wi  = (const float*)d_in[1];
    const float* bi  = (const float*)d_in[2];
    const float* Wf  = (const float*)d_in[3];
    const float* bf  = (const float*)d_in[4];
    const float* Wg  = (const float*)d_in[5];
    const float* bg  = (const float*)d_in[6];
    const float* Wr  = (const float*)d_in[7];
    const float* br  = (const float*)d_in[8];
    const float* W1  = (const float*)d_in[9];
    const float* b1  = (const float*)d_in[10];
    const float* W2  = (const float*)d_in[11];
    const float* b2  = (const float*)d_in[12];
    float* out = (float*)d_out;

    cudaFuncSetAttribute(in_mma,     cudaFuncAttributeMaxDynamicSharedMemorySize, INM_SMEM);
    cudaFuncSetAttribute(layer_mma,  cudaFuncAttributeMaxDynamicSharedMemorySize, LMM_SMEM);
    cudaFuncSetAttribute(head_fused, cudaFuncAttributeMaxDynamicSharedMemorySize, HF_SMEM);

    prep_w<<<1024, 256>>>(Wf, Wg, Wr, W1, W2, Wi);
    in_mma<<<dim3(T0/64, NB), 256, INM_SMEM>>>(inp, bi);

    static const int dil[NLAY] = {1,2,4,8,16,32,64,128,256,512,
                                  1,2,4,8,16,32,64,128,256,512};
    int Tcur = T0;
    for (int l = 0; l < NLAY; l++) {
        int d = dil[l];
        int Tnew = Tcur - d;
        int ssel = (l == 0) ? 2 : ((l - 1) & 1);
        int dsel = l & 1;
        dim3 g((Tnew + 63) / 64, NB);
        const float* pbf = bf + l * 128;
        const float* pbg = bg + l * 128;
        const float* pbr = br + l * 128;
        void* args[] = { &ssel, &dsel, &l, &pbf, &pbg, &pbr, &d, &Tnew };
        launch_pdl((void*)layer_mma, g, dim3(256), LMM_SMEM, args);
        Tcur = Tnew;
    }
    // after 20 layers, res_final is in g_res1 (dsel of layer 19 = 1)

    {
        dim3 g((TARGET + 31) / 32, NB);
        const float* pb1 = b1;
        const float* pb2 = b2;
        void* args[] = { &pb1, &pb2, &out };
        launch_pdl((void*)head_fused, g, dim3(256), HF_SMEM, args);
    }
}

// round 17
// speedup vs baseline: 1.1147x; 1.1147x over previous
#include <cuda_runtime.h>
#include <cuda_fp16.h>
#include <math.h>
#include <stdint.h>

typedef unsigned long long u64;
typedef unsigned int u32;

#define NB      8
#define T0      8192
#define HID     128
#define TARGET  6146
#define NLAY    20

// ---------------- scratch (device globals; no allocation) ----------------
__device__ float  g_resI[(size_t)NB * T0 * HID];   // input projection (preserved)
__device__ float  g_res0[(size_t)NB * T0 * HID];
__device__ float  g_res1[(size_t)NB * T0 * HID];
// fragment-ordered fp16 weights
__device__ u32 g_wfrag1[(size_t)NLAY * 32768]; // [l][mat][tile16][kc][ks][lane][4]
__device__ u32 g_wfrag2[(size_t)NLAY * 8192];  // [l][c][ks][mt][lane][4]
__device__ u32 g_whi[16384];                   // Wi frags [tile8][kc8][ks2][lane][4]
__device__ u32 g_wh1[32768];
__device__ u32 g_wh2[65536];

// ---------------- PDL helpers (sm_90 baseline PTX) ----------------
#define PDL_TRIGGER() asm volatile("griddepcontrol.launch_dependents;" ::: "memory")
#define PDL_WAIT()    asm volatile("griddepcontrol.wait;" ::: "memory")

// ---------------- fp16 mma helpers ----------------
__device__ __forceinline__ u32 pkhalf2(float lo, float hi) {
    u32 u;
    asm("{ .reg .b16 l, h; cvt.rn.f16.f32 l, %1; cvt.rn.f16.f32 h, %2; mov.b32 %0, {l, h}; }"
        : "=r"(u) : "f"(lo), "f"(hi));
    return u;
}
__device__ __forceinline__ void mma16816(float* c, const u32* a, u32 b0, u32 b1) {
    asm volatile(
        "mma.sync.aligned.m16n8k16.row.col.f32.f16.f16.f32 "
        "{%0,%1,%2,%3}, {%4,%5,%6,%7}, {%8,%9}, {%0,%1,%2,%3};"
        : "+f"(c[0]), "+f"(c[1]), "+f"(c[2]), "+f"(c[3])
        : "r"(a[0]), "r"(a[1]), "r"(a[2]), "r"(a[3]), "r"(b0), "r"(b1));
}
__device__ __forceinline__ void ldm_x4(u32* r, u32 addr) {
    asm volatile("ldmatrix.sync.aligned.m8n8.x4.shared.b16 {%0,%1,%2,%3}, [%4];"
        : "=r"(r[0]), "=r"(r[1]), "=r"(r[2]), "=r"(r[3]) : "r"(addr));
}
__device__ __forceinline__ u32 h2tanh(u32 x) {
    u32 y; asm("tanh.approx.f16x2 %0, %1;" : "=r"(y) : "r"(x)); return y;
}
__device__ __forceinline__ u32 h2fma(u32 a, u32 b, u32 c) {
    u32 d; asm("fma.rn.f16x2 %0, %1, %2, %3;" : "=r"(d) : "r"(a), "r"(b), "r"(c)); return d;
}
__device__ __forceinline__ u32 h2mul(u32 a, u32 b) {
    u32 d; asm("mul.rn.f16x2 %0, %1, %2;" : "=r"(d) : "r"(a), "r"(b)); return d;
}
__device__ __forceinline__ uint32_t smem_u32(const void* p) {
    uint32_t a;
    asm("{ .reg .u64 t; cvta.to.shared.u64 t, %1; cvt.u32.u64 %0, t; }" : "=r"(a) : "l"(p));
    return a;
}

// =====================================================================
// Weight prep: fp32 -> fp16 fragment order, once per launch
// =====================================================================
__global__ __launch_bounds__(256) void prep_w(
    const float* __restrict__ Wf, const float* __restrict__ Wg,
    const float* __restrict__ Wr, const float* __restrict__ W1,
    const float* __restrict__ W2, const float* __restrict__ Wi)
{
    const int stride = gridDim.x * blockDim.x;
    const int tid0 = blockIdx.x * blockDim.x + threadIdx.x;
    // GEMM1 frags: [l][mat][tile16][kc][ks][lane][reg], k-index = 2*i+tap
    for (int idx = tid0; idx < NLAY * 32768; idx += stride) {
        int l = idx >> 15, r = idx & 32767;
        int mat  = (r >> 14) & 1;
        int tile = (r >> 11) & 7;
        int kc   = (r >> 8) & 7;
        int ks   = (r >> 7) & 1;
        int lane = (r >> 2) & 31;
        int reg  = r & 3;
        int row = tile * 16 + (lane >> 2) + ((reg & 1) ? 8 : 0);
        int kb  = kc * 32 + ks * 16 + 2 * (lane & 3) + ((reg & 2) ? 8 : 0);
        const float* W = (mat ? Wg : Wf) + (size_t)l * 32768;
        float2 v = *(const float2*)(W + ((size_t)row * 128 + (kb >> 1)) * 2);
        g_wfrag1[idx] = pkhalf2(v.x, v.y);
    }
    // GEMM2 frags
    for (int idx = tid0; idx < NLAY * 8192; idx += stride) {
        int l = idx >> 13, r = idx & 8191;
        int c  = (r >> 11) & 3;
        int ks = (r >> 8) & 7;
        int mt = (r >> 7) & 1;
        int lane = (r >> 2) & 31;
        int reg  = r & 3;
        int row = c * 32 + mt * 16 + (lane >> 2) + ((reg & 1) ? 8 : 0);
        int k   = ks * 16 + 2 * (lane & 3) + ((reg & 2) ? 8 : 0);
        const float* W = Wr + (size_t)l * 16384;
        g_wfrag2[idx] = pkhalf2(W[row * 128 + k], W[row * 128 + k + 1]);
    }
    // Wi frags: [tile8][kc8][ks2][lane][reg], K=256
    for (int idx = tid0; idx < 16384; idx += stride) {
        int tile = (idx >> 11) & 7;
        int kc   = (idx >> 8) & 7;
        int ks   = (idx >> 7) & 1;
        int lane = (idx >> 2) & 31;
        int reg  = idx & 3;
        int row = tile * 16 + (lane >> 2) + ((reg & 1) ? 8 : 0);
        int k   = kc * 32 + ks * 16 + 2 * (lane & 3) + ((reg & 2) ? 8 : 0);
        g_whi[idx] = pkhalf2(Wi[row * 256 + k], Wi[row * 256 + k + 1]);
    }
    // head1 frags: W1 [512][128]
    for (int idx = tid0; idx < 32768; idx += stride) {
        int tile = idx >> 10;
        int ks   = (idx >> 7) & 7;
        int lane = (idx >> 2) & 31;
        int reg  = idx & 3;
        int row = tile * 16 + (lane >> 2) + ((reg & 1) ? 8 : 0);
        int k   = ks * 16 + 2 * (lane & 3) + ((reg & 2) ? 8 : 0);
        g_wh1[idx] = pkhalf2(W1[row * 128 + k], W1[row * 128 + k + 1]);
    }
    // head2 frags: W2 [256][512]
    for (int idx = tid0; idx < 65536; idx += stride) {
        int tile = idx >> 12;
        int ks   = (idx >> 7) & 31;
        int lane = (idx >> 2) & 31;
        int reg  = idx & 3;
        int row = tile * 16 + (lane >> 2) + ((reg & 1) ? 8 : 0);
        int k   = ks * 16 + 2 * (lane & 3) + ((reg & 2) ? 8 : 0);
        g_wh2[idx] = pkhalf2(W2[row * 512 + k], W2[row * 512 + k + 1]);
    }
}

// smem byte map for layer_mma
#define SM_ACT  0
#define SM_OUT  33792
#define LMM_SMEM (SM_OUT + 17408)   // 51200

// =====================================================================
// Layer kernel (R15 structure) + minimal PDL (no prefetch payload)
// ssel: 2 = g_resI, 0 = g_res0, 1 = g_res1; dsel: 0/1
// =====================================================================
__global__ __launch_bounds__(256, 2) void layer_mma(
    int ssel, int dsel, int layer,
    const float* __restrict__ bf, const float* __restrict__ bg,
    const float* __restrict__ br,
    int d, int Tnew)
{
    extern __shared__ char sm[];
    const u32 sb = smem_u32(sm);

    const int tid = threadIdx.x, wid = tid >> 5, lane = tid & 31;
    const int g8 = lane >> 2, tig = lane & 3;
    const int b = blockIdx.y, t0 = blockIdx.x * 64;
    const int Tcur = Tnew + d;

    PDL_WAIT();   // prior layer fully visible from here

    const float* srcb = (ssel == 2 ? g_resI : (ssel ? g_res1 : g_res0)) + (size_t)b * T0 * HID;
    float*       dstb = (dsel ? g_res1 : g_res0) + (size_t)b * T0 * HID;

    // ---- stage activations, taps interleaved: s_act[t][k=2c+tap] ----
    for (int e = tid; e < 64 * 32; e += 256) {
        int j = e >> 5, c4 = e & 31;
        int ta = t0 + j;     if (ta > Tcur - 1) ta = Tcur - 1;
        int tb = t0 + j + d; if (tb > Tcur - 1) tb = Tcur - 1;
        float4 A = *(const float4*)(srcb + (size_t)ta * HID + c4 * 4);
        float4 B = *(const float4*)(srcb + (size_t)tb * HID + c4 * 4);
        uint4 st;
        st.x = pkhalf2(A.x, B.x);
        st.y = pkhalf2(A.y, B.y);
        st.z = pkhalf2(A.z, B.z);
        st.w = pkhalf2(A.w, B.w);
        *(uint4*)(sm + SM_ACT + j * 528 + c4 * 16) = st;
    }
    __syncthreads();   // #1

    const int browoff = ((lane & 16) ? 8 : 0) + (lane & 7);
    const u32 bk16 = (lane & 8) ? 16u : 0u;
    const u32 b_base = sb + SM_ACT + browoff * 528 + bk16;

    // ---- GEMM1: warp w computes f AND g for ch [16w,16w+16) x 64 t ----
    const uint4* wpf = (const uint4*)g_wfrag1 + (size_t)layer * 8192 + wid * 512 + lane;
    const uint4* wpg = wpf + 4096;

    float acc_f[8][4], acc_g[8][4];
#pragma unroll
    for (int i = 0; i < 8; i++)
#pragma unroll
        for (int k = 0; k < 4; k++) { acc_f[i][k] = 0.f; acc_g[i][k] = 0.f; }

    uint4 Af[2], Ag[2];
    Af[0] = wpf[0]; Af[1] = wpf[32]; Ag[0] = wpg[0]; Ag[1] = wpg[32];
    for (int kc = 0; kc < 8; kc++) {
        uint4 Afn[2], Agn[2];
        if (kc < 7) {
            Afn[0] = wpf[(kc + 1) * 64];      Afn[1] = wpf[(kc + 1) * 64 + 32];
            Agn[0] = wpg[(kc + 1) * 64];      Agn[1] = wpg[(kc + 1) * 64 + 32];
        }
        const u32 bbase_k = b_base + kc * 64;
#pragma unroll
        for (int ks = 0; ks < 2; ks++) {
            const u32* af = (const u32*)&Af[ks];
            const u32* ag = (const u32*)&Ag[ks];
#pragma unroll
            for (int ntp = 0; ntp < 4; ntp++) {
                u32 bt[4];
                ldm_x4(bt, bbase_k + ntp * 8448 + ks * 32);
                mma16816(acc_f[2 * ntp],     af, bt[0], bt[1]);
                mma16816(acc_f[2 * ntp + 1], af, bt[2], bt[3]);
                mma16816(acc_g[2 * ntp],     ag, bt[0], bt[1]);
                mma16816(acc_g[2 * ntp + 1], ag, bt[2], bt[3]);
            }
        }
        if (kc < 7) { Af[0] = Afn[0]; Af[1] = Afn[1]; Ag[0] = Agn[0]; Ag[1] = Agn[1]; }
    }

    // bulk work done: allow the next grid to launch/setup
    PDL_TRIGGER();

    // ---- early GEMM2 A-fragment prefetch (hides L2 latency behind epilogue) ----
    const uint4* wp2 = (const uint4*)g_wfrag2 +
        (size_t)layer * 2048 + (wid & 3) * 512 + lane;
    uint4 A2[2];
    A2[0] = wp2[0]; A2[1] = wp2[32];

    // ---- epilogue1 (f16x2): out = tanh(f+bf) * (.5 + .5*tanh(.5*(g+bg))) ----
    {
        unsigned short* sout = (unsigned short*)(sm + SM_OUT);
        const int ch0 = wid * 16 + g8;
        float bf0 = bf[ch0], bf8 = bf[ch0 + 8];
        float bg0h = 0.5f * bg[ch0], bg8h = 0.5f * bg[ch0 + 8];
        const u32 H05 = 0x38003800u;
#pragma unroll
        for (int nt = 0; nt < 8; nt++) {
            int t_ = nt * 8 + 2 * tig;
            u32 tf01 = h2tanh(pkhalf2(acc_f[nt][0] + bf0, acc_f[nt][1] + bf0));
            u32 tf23 = h2tanh(pkhalf2(acc_f[nt][2] + bf8, acc_f[nt][3] + bf8));
            u32 tg01 = h2tanh(pkhalf2(fmaf(acc_g[nt][0], 0.5f, bg0h),
                                      fmaf(acc_g[nt][1], 0.5f, bg0h)));
            u32 tg23 = h2tanh(pkhalf2(fmaf(acc_g[nt][2], 0.5f, bg8h),
                                      fmaf(acc_g[nt][3], 0.5f, bg8h)));
            u32 p01 = h2mul(tf01, h2fma(tg01, H05, H05));
            u32 p23 = h2mul(tf23, h2fma(tg23, H05, H05));
            unsigned short lo, hi;
            asm("mov.b32 {%0, %1}, %2;" : "=h"(lo), "=h"(hi) : "r"(p01));
            sout[(t_    ) * 136 + ch0] = lo;
            sout[(t_ + 1) * 136 + ch0] = hi;
            asm("mov.b32 {%0, %1}, %2;" : "=h"(lo), "=h"(hi) : "r"(p23));
            sout[(t_    ) * 136 + ch0 + 8] = lo;
            sout[(t_ + 1) * 136 + ch0 + 8] = hi;
        }
    }
    __syncthreads();   // #2

    // ---- GEMM2: x = Wr . out ----
    const int chb2 = (wid & 3) * 32;
    const int nb2 = (wid >> 2) * 32;
    const u32 b2base = sb + SM_OUT + (nb2 + browoff) * 272 + bk16;

    float acc2[8][4];
#pragma unroll
    for (int i = 0; i < 8; i++)
#pragma unroll
        for (int k = 0; k < 4; k++) acc2[i][k] = 0.f;

    for (int ks = 0; ks < 8; ks++) {
        uint4 A2n[2];
        if (ks < 7) { A2n[0] = wp2[(ks + 1) * 64]; A2n[1] = wp2[(ks + 1) * 64 + 32]; }
#pragma unroll
        for (int ntp = 0; ntp < 2; ntp++) {
            u32 bt[4];
            ldm_x4(bt, b2base + ntp * 4352 + ks * 32);
            mma16816(acc2[ntp * 2],         (const u32*)&A2[0], bt[0], bt[1]);
            mma16816(acc2[ntp * 2 + 1],     (const u32*)&A2[0], bt[2], bt[3]);
            mma16816(acc2[4 + ntp * 2],     (const u32*)&A2[1], bt[0], bt[1]);
            mma16816(acc2[4 + ntp * 2 + 1], (const u32*)&A2[1], bt[2], bt[3]);
        }
        if (ks < 7) { A2[0] = A2n[0]; A2[1] = A2n[1]; }
    }

    // ---- epilogue2: x + br -> s_x ----
    float* sx = (float*)(sm + SM_ACT);
    {
        float br0 = br[chb2 + g8],       br8  = br[chb2 + g8 + 8];
        float br16 = br[chb2 + 16 + g8], br24 = br[chb2 + 24 + g8];
#pragma unroll
        for (int mt = 0; mt < 2; mt++) {
            int ch0 = chb2 + mt * 16 + g8;
            float bv0 = mt ? br16 : br0;
            float bv8 = mt ? br24 : br8;
#pragma unroll
            for (int nt = 0; nt < 4; nt++) {
                int t_ = nb2 + nt * 8 + 2 * tig;
                float* a4 = acc2[mt * 4 + nt];
                sx[(t_    ) * 132 + ch0    ] = a4[0] + bv0;
                sx[(t_ + 1) * 132 + ch0    ] = a4[1] + bv0;
                sx[(t_    ) * 132 + ch0 + 8] = a4[2] + bv8;
                sx[(t_ + 1) * 132 + ch0 + 8] = a4[3] + bv8;
            }
        }
    }

    // ---- hoisted residual loads (overlap with barrier #3) ----
    float4 rv[8];
#pragma unroll
    for (int it = 0; it < 8; it++) {
        int e = tid + it * 256;
        int j = e >> 5, c4 = e & 31;
        int t = t0 + j;
        int tt = (t < Tnew) ? (t + d) : (Tcur - 1);
        rv[it] = *(const float4*)(srcb + (size_t)tt * HID + c4 * 4);
    }
    __syncthreads();   // #3

    // ---- residual only (skip telescoped away) ----
#pragma unroll
    for (int it = 0; it < 8; it++) {
        int e = tid + it * 256;
        int j = e >> 5, c4 = e & 31;
        int t = t0 + j;
        if (t < Tnew) {
            float4 x = *(float4*)(sx + j * 132 + c4 * 4);
            float4 o;
            o.x = x.x + rv[it].x; o.y = x.y + rv[it].y;
            o.z = x.z + rv[it].z; o.w = x.w + rv[it].w;
            *(float4*)(dstb + (size_t)t * HID + c4 * 4) = o;
        }
    }
}

// =====================================================================
// Input GEMM (mma): resI = Wi . inputs + bi, 128ch x 64t per CTA, K=256
// =====================================================================
#define INM_SMEM (64 * 528)
__global__ __launch_bounds__(256, 2) void in_mma(
    const float* __restrict__ inp, const float* __restrict__ bi)
{
    extern __shared__ char sm[];
    const u32 sb = smem_u32(sm);
    const int tid = threadIdx.x, wid = tid >> 5, lane = tid & 31;
    const int g8 = lane >> 2, tig = lane & 3;
    const int b = blockIdx.y, t0 = blockIdx.x * 64;

    const float* ib = inp + (size_t)b * 256 * T0;
    // stage: smem half[64t][264], k = ch (coalesced along t)
    for (int e = tid; e < 1024; e += 256) {
        int cblk = e >> 4, tq = e & 15;
        const float* p0 = ib + (size_t)(cblk * 4) * T0 + t0 + tq * 4;
        float4 r0 = *(const float4*)(p0);
        float4 r1 = *(const float4*)(p0 + T0);
        float4 r2 = *(const float4*)(p0 + 2 * T0);
        float4 r3 = *(const float4*)(p0 + 3 * T0);
        const float* f0 = (const float*)&r0;
        const float* f1 = (const float*)&r1;
        const float* f2 = (const float*)&r2;
        const float* f3 = (const float*)&r3;
#pragma unroll
        for (int tt = 0; tt < 4; tt++) {
            uint2 st;
            st.x = pkhalf2(f0[tt], f1[tt]);
            st.y = pkhalf2(f2[tt], f3[tt]);
            *(uint2*)(sm + (tq * 4 + tt) * 528 + cblk * 8) = st;
        }
    }
    __syncthreads();

    const int browoff = ((lane & 16) ? 8 : 0) + (lane & 7);
    const u32 bk16 = (lane & 8) ? 16u : 0u;
    const u32 b_base = sb + browoff * 528 + bk16;
    const uint4* wpA = (const uint4*)g_whi + wid * 512 + lane;

    float acc[8][4];
#pragma unroll
    for (int i = 0; i < 8; i++)
#pragma unroll
        for (int k = 0; k < 4; k++) acc[i][k] = 0.f;

    uint4 A[2] = { wpA[0], wpA[32] };
    for (int kc = 0; kc < 8; kc++) {
        uint4 An[2];
        if (kc < 7) { An[0] = wpA[(kc + 1) * 64]; An[1] = wpA[(kc + 1) * 64 + 32]; }
        const u32 bbase_k = b_base + kc * 64;
#pragma unroll
        for (int ks = 0; ks < 2; ks++) {
            const u32* af = (const u32*)&A[ks];
#pragma unroll
            for (int ntp = 0; ntp < 4; ntp++) {
                u32 bt[4];
                ldm_x4(bt, bbase_k + ntp * 8448 + ks * 32);
                mma16816(acc[2 * ntp],     af, bt[0], bt[1]);
                mma16816(acc[2 * ntp + 1], af, bt[2], bt[3]);
            }
        }
        if (kc < 7) { A[0] = An[0]; A[1] = An[1]; }
    }

    // mainloop done: allow layer 0 to launch/setup
    PDL_TRIGGER();

    float* rb = g_resI + (size_t)b * T0 * HID;
    const int ch0 = wid * 16 + g8;
    const float bv0 = bi[ch0], bv8 = bi[ch0 + 8];
#pragma unroll
    for (int nt = 0; nt < 8; nt++) {
        int t_ = t0 + nt * 8 + 2 * tig;
        rb[(size_t)t_ * HID + ch0]           = acc[nt][0] + bv0;
        rb[(size_t)(t_ + 1) * HID + ch0]     = acc[nt][1] + bv0;
        rb[(size_t)t_ * HID + ch0 + 8]       = acc[nt][2] + bv8;
        rb[(size_t)(t_ + 1) * HID + ch0 + 8] = acc[nt][3] + bv8;
    }
}

// =====================================================================
// Fused head: out = W2.relu(W1.relu(resF - resI_shift)+b1)+b2  (+PDL wait)
// =====================================================================
#define HF_SIN  0
#define HF_SMID 8704
#define HF_SMEM (HF_SMID + 32 * 1040)   // 41984
__global__ __launch_bounds__(256, 2) void head_fused(
    const float* __restrict__ b1, const float* __restrict__ b2,
    float* __restrict__ out)
{
    extern __shared__ char sm[];
    const u32 sb = smem_u32(sm);
    const int tid = threadIdx.x, wid = tid >> 5, lane = tid & 31;
    const int g8 = lane >> 2, tig = lane & 3;
    const int b = blockIdx.y, t0 = blockIdx.x * 32;

    PDL_WAIT();

    // ---- phase A input: relu(resF - resI_shift) -> fp16 smem ----
    const float* rf = g_res1 + (size_t)b * T0 * HID;
    const float* ri = g_resI + (size_t)b * T0 * HID + (size_t)(T0 - TARGET) * HID;
    for (int e = tid; e < 32 * 32; e += 256) {
        int j = e >> 5, c4 = e & 31;
        int t = t0 + j;
        float4 v = make_float4(0.f, 0.f, 0.f, 0.f);
        if (t < TARGET) {
            float4 a = *(const float4*)(rf + (size_t)t * HID + c4 * 4);
            float4 c = *(const float4*)(ri + (size_t)t * HID + c4 * 4);
            v.x = a.x - c.x; v.y = a.y - c.y; v.z = a.z - c.z; v.w = a.w - c.w;
        }
        uint2 st;
        st.x = pkhalf2(fmaxf(v.x, 0.f), fmaxf(v.y, 0.f));
        st.y = pkhalf2(fmaxf(v.z, 0.f), fmaxf(v.w, 0.f));
        *(uint2*)(sm + HF_SIN + j * 272 + c4 * 8) = st;
    }
    __syncthreads();

    const int browoff = ((lane & 16) ? 8 : 0) + (lane & 7);
    const u32 bk16 = (lane & 8) ? 16u : 0u;

    // ---- head1 GEMM: warp w -> 64 mid-ch x 32 t, K=128 ----
    {
        const u32 b_base = sb + HF_SIN + browoff * 272 + bk16;
        const uint4* wp = (const uint4*)g_wh1 + wid * 4 * 256 + lane;

        float acc[16][4];
#pragma unroll
        for (int i = 0; i < 16; i++)
#pragma unroll
            for (int k = 0; k < 4; k++) acc[i][k] = 0.f;

        uint4 A[4];
#pragma unroll
        for (int mt = 0; mt < 4; mt++) A[mt] = wp[mt * 256];
        for (int ks = 0; ks < 8; ks++) {
            uint4 An[4];
            if (ks < 7) {
#pragma unroll
                for (int mt = 0; mt < 4; mt++) An[mt] = wp[mt * 256 + (ks + 1) * 32];
            }
#pragma unroll
            for (int ntp = 0; ntp < 2; ntp++) {
                u32 bt[4];
                ldm_x4(bt, b_base + ntp * 4352 + ks * 32);
#pragma unroll
                for (int mt = 0; mt < 4; mt++) {
                    mma16816(acc[mt * 4 + 2 * ntp],     (const u32*)&A[mt], bt[0], bt[1]);
                    mma16816(acc[mt * 4 + 2 * ntp + 1], (const u32*)&A[mt], bt[2], bt[3]);
                }
            }
            if (ks < 7) {
#pragma unroll
                for (int mt = 0; mt < 4; mt++) A[mt] = An[mt];
            }
        }

        // mid = relu(acc + b1) -> fp16 smem (same rounding as before)
        __half* smd = (__half*)(sm + HF_SMID);
#pragma unroll
        for (int mt = 0; mt < 4; mt++) {
            int ch0 = wid * 64 + mt * 16 + g8;
            float bv0 = b1[ch0], bv8 = b1[ch0 + 8];
#pragma unroll
            for (int nt = 0; nt < 4; nt++) {
                int t_ = nt * 8 + 2 * tig;
                float* a4 = acc[mt * 4 + nt];
                smd[(t_    ) * 520 + ch0    ] = __float2half_rn(fmaxf(a4[0] + bv0, 0.f));
                smd[(t_ + 1) * 520 + ch0    ] = __float2half_rn(fmaxf(a4[1] + bv0, 0.f));
                smd[(t_    ) * 520 + ch0 + 8] = __float2half_rn(fmaxf(a4[2] + bv8, 0.f));
                smd[(t_ + 1) * 520 + ch0 + 8] = __float2half_rn(fmaxf(a4[3] + bv8, 0.f));
            }
        }
    }
    __syncthreads();

    // ---- head2 GEMM: warp w -> out-ch tiles {2w, 2w+1} x 32 t, K=512 ----
    {
        const u32 b2b = sb + HF_SMID + browoff * 1040 + bk16;
        const uint4* wp0 = (const uint4*)g_wh2 + (wid * 2) * 1024 + lane;
        const uint4* wp1 = wp0 + 1024;

        float acc2[8][4];
#pragma unroll
        for (int i = 0; i < 8; i++)
#pragma unroll
            for (int k = 0; k < 4; k++) acc2[i][k] = 0.f;

        uint4 A[2] = { wp0[0], wp1[0] };
        for (int ks = 0; ks < 32; ks++) {
            uint4 An[2];
            if (ks < 31) { An[0] = wp0[(ks + 1) * 32]; An[1] = wp1[(ks + 1) * 32]; }
#pragma unroll
            for (int ntp = 0; ntp < 2; ntp++) {
                u32 bt[4];
                ldm_x4(bt, b2b + ntp * 16640 + ks * 32);
                mma16816(acc2[ntp * 2],         (const u32*)&A[0], bt[0], bt[1]);
                mma16816(acc2[ntp * 2 + 1],     (const u32*)&A[0], bt[2], bt[3]);
                mma16816(acc2[4 + ntp * 2],     (const u32*)&A[1], bt[0], bt[1]);
                mma16816(acc2[4 + ntp * 2 + 1], (const u32*)&A[1], bt[2], bt[3]);
            }
            if (ks < 31) { A[0] = An[0]; A[1] = An[1]; }
        }

#pragma unroll
        for (int j = 0; j < 2; j++) {
            int ch0 = (wid * 2 + j) * 16 + g8;
            float bv0 = b2[ch0], bv8 = b2[ch0 + 8];
#pragma unroll
            for (int nt = 0; nt < 4; nt++) {
                int t_ = t0 + nt * 8 + 2 * tig;
                float* a4 = acc2[j * 4 + nt];
                if (t_ < TARGET) {
                    float* op = out + ((size_t)b * TARGET + t_) * 256;
                    op[ch0]     = a4[0] + bv0;
                    op[ch0 + 8] = a4[2] + bv8;
                }
                if (t_ + 1 < TARGET) {
                    float* op = out + ((size_t)b * TARGET + t_ + 1) * 256;
                    op[ch0]     = a4[1] + bv0;
                    op[ch0 + 8] = a4[3] + bv8;
                }
            }
        }
    }
}

// =====================================================================
// Host launcher
// =====================================================================
static void launch_pdl(void* fn, dim3 grid, dim3 block, size_t smem,
                       void** args)
{
    cudaLaunchConfig_t cfg = {};
    cfg.gridDim = grid;
    cfg.blockDim = block;
    cfg.dynamicSmemBytes = smem;
    cfg.stream = 0;
    cudaLaunchAttribute attr[1];
    attr[0].id = cudaLaunchAttributeProgrammaticStreamSerialization;
    attr[0].val.programmaticStreamSerializationAllowed = 1;
    cfg.attrs = attr;
    cfg.numAttrs = 1;
    cudaLaunchKernelExC(&cfg, fn, args);
}

extern "C" void kernel_launch(void* const* d_in, const int* in_sizes, int n_in,
                              void* d_out, int out_size)
{
    (void)in_sizes; (void)n_in; (void)out_size;
    const float* inp = (const float*)d_in[0];
    const float* Wi  = (const float*)d_in[1];
    const float* bi  = (const float*)d_in[2];
    const float* Wf  = (const float*)d_in[3];
    const float* bf  = (const float*)d_in[4];
    const float* Wg  = (const float*)d_in[5];
    const float* bg  = (const float*)d_in[6];
    const float* Wr  = (const float*)d_in[7];
    const float* br  = (const float*)d_in[8];
    const float* W1  = (const float*)d_in[9];
    const float* b1  = (const float*)d_in[10];
    const float* W2  = (const float*)d_in[11];
    const float* b2  = (const float*)d_in[12];
    float* out = (float*)d_out;

    cudaFuncSetAttribute(in_mma,     cudaFuncAttributeMaxDynamicSharedMemorySize, INM_SMEM);
    cudaFuncSetAttribute(layer_mma,  cudaFuncAttributeMaxDynamicSharedMemorySize, LMM_SMEM);
    cudaFuncSetAttribute(head_fused, cudaFuncAttributeMaxDynamicSharedMemorySize, HF_SMEM);

    prep_w<<<1024, 256>>>(Wf, Wg, Wr, W1, W2, Wi);
    in_mma<<<dim3(T0/64, NB), 256, INM_SMEM>>>(inp, bi);

    static const int dil[NLAY] = {1,2,4,8,16,32,64,128,256,512,
                                  1,2,4,8,16,32,64,128,256,512};
    int Tcur = T0;
    for (int l = 0; l < NLAY; l++) {
        int d = dil[l];
        int Tnew = Tcur - d;
        int ssel = (l == 0) ? 2 : ((l - 1) & 1);
        int dsel = l & 1;
        dim3 g((Tnew + 63) / 64, NB);
        const float* pbf = bf + l * 128;
        const float* pbg = bg + l * 128;
        const float* pbr = br + l * 128;
        void* args[] = { &ssel, &dsel, &l, &pbf, &pbg, &pbr, &d, &Tnew };
        launch_pdl((void*)layer_mma, g, dim3(256), LMM_SMEM, args);
        Tcur = Tnew;
    }
    // after 20 layers, res_final is in g_res1 (dsel of layer 19 = 1)

    {
        dim3 g((TARGET + 31) / 32, NB);
        const float* pb1 = b1;
        const float* pb2 = b2;
        void* args[] = { &pb1, &pb2, &out };
        launch_pdl((void*)head_fused, g, dim3(256), HF_SMEM, args);
    }
}